// round 14
// baseline (speedup 1.0000x reference)
#include <cuda_runtime.h>
#include <cstdint>

#define NN 65536
#define KK 8192
#define DD 256
#define BM 64
#define ALD 68           // padded A row stride (u32): swizzled cols 0..67
#define BN 128
#define NTT (KK/BN)      // 64 n-tiles
#define NCH 8            // chunks of 8 d4 (32 dims)
#define MARGIN 6.0e-4f
#define CAP 8

// smem byte offsets
#define SM_A     0          // u32[64 d4][68] (col-swizzled)    17408
#define SM_B     17408      // u32[2][8 dl][128 n]               8192
#define SM_CAND  25600      // u16[64 m][16 sub][CAP]           16384
#define SM_CNT   41984      // u8[64][16]                        1024
#define SM_OVFN  43008
#define SM_OVFR  43012      // int[64]
#define SM_PACK  43272      // 8B aligned
#define SMEM_BYTES 43280

__device__ float    g_z2[NN];
__device__ float    g_e2[KK];
__device__ float    g_sz[NN];        // z row scale (amax/127)
__device__ float    g_se2[KK];       // -2 * e row scale
__device__ int      g_idx[NN];
__device__ uint32_t g_zq[(size_t)NN * (DD/4)];          // packed int8 [n][d4]
__device__ uint32_t g_eqT[(size_t)(DD/4) * KK];         // packed int8 [d4][k]

// A column placement: chunk mc (m = mc*8..mc*8+7) at column mc*8 + 4*(mc>>2).
// Bank-group bases {0,8,16,24,4,12,20,28} — all distinct, conflict-free
// LDS.128; max col = 56+4+7 = 67 < ALD.
__device__ __forceinline__ int swzA(int m) {
    int mc = m >> 3;
    return mc * 8 + ((mc >> 2) << 2) + (m & 7);
}

__device__ __forceinline__ uint32_t pack4(const float* v, float qs) {
    uint32_t r = 0;
    #pragma unroll
    for (int i = 0; i < 4; ++i) {
        int q = __float2int_rn(v[i] * qs);
        q = max(-127, min(127, q));
        r |= (uint32_t)(q & 0xff) << (i * 8);
    }
    return r;
}

// ---------------- prep kernels (proven) ----------------
__global__ void prep_z_kernel(const float* __restrict__ x) {
    int row  = blockIdx.x * 8 + (threadIdx.x >> 5);
    int lane = threadIdx.x & 31;
    const float* p = x + (size_t)row * DD;
    double s = 0.0;
    #pragma unroll
    for (int i = 0; i < DD / 32; ++i) {
        float v = p[lane + i * 32];
        float q = v * v;
        s += (double)q;
    }
    #pragma unroll
    for (int o = 16; o; o >>= 1) s += __shfl_xor_sync(0xffffffffu, s, o);
    if (lane == 0) g_z2[row] = (float)s;
    const float4* p4 = (const float4*)p;
    float4 v0 = p4[lane * 2], v1 = p4[lane * 2 + 1];
    float v[8] = {v0.x, v0.y, v0.z, v0.w, v1.x, v1.y, v1.z, v1.w};
    float amax = 0.0f;
    #pragma unroll
    for (int i = 0; i < 8; ++i) amax = fmaxf(amax, fabsf(v[i]));
    #pragma unroll
    for (int o = 16; o; o >>= 1) amax = fmaxf(amax, __shfl_xor_sync(0xffffffffu, amax, o));
    float qs = amax > 0.0f ? 127.0f / amax : 0.0f;
    g_zq[(size_t)row * 64 + lane * 2]     = pack4(v, qs);
    g_zq[(size_t)row * 64 + lane * 2 + 1] = pack4(v + 4, qs);
    if (lane == 0) g_sz[row] = amax * (1.0f / 127.0f);
}

__global__ void row_norm_kernel(const float* __restrict__ x, int which) {
    int row  = blockIdx.x * 8 + (threadIdx.x >> 5);
    int lane = threadIdx.x & 31;
    const float* p = x + (size_t)row * DD;
    double s = 0.0;
    #pragma unroll
    for (int i = 0; i < DD / 32; ++i) {
        float v = p[lane + i * 32];
        float q = v * v;
        s += (double)q;
    }
    #pragma unroll
    for (int o = 16; o; o >>= 1) s += __shfl_xor_sync(0xffffffffu, s, o);
    if (lane == 0) { if (which) g_e2[row] = (float)s; else g_z2[row] = (float)s; }
}

__global__ void quant_eT_kernel(const float* __restrict__ e) {
    __shared__ uint32_t ts[64][33];
    int tid = threadIdx.x, wid = tid >> 5, lane = tid & 31;
    int k0 = blockIdx.x * 32;
    #pragma unroll
    for (int r = 0; r < 4; ++r) {
        int kl = wid * 4 + r;
        int k = k0 + kl;
        const float4* p = (const float4*)(e + (size_t)k * DD);
        float4 v0 = p[lane * 2], v1 = p[lane * 2 + 1];
        float v[8] = {v0.x, v0.y, v0.z, v0.w, v1.x, v1.y, v1.z, v1.w};
        float amax = 0.0f;
        #pragma unroll
        for (int i = 0; i < 8; ++i) amax = fmaxf(amax, fabsf(v[i]));
        #pragma unroll
        for (int o = 16; o; o >>= 1) amax = fmaxf(amax, __shfl_xor_sync(0xffffffffu, amax, o));
        float qs = amax > 0.0f ? 127.0f / amax : 0.0f;
        ts[lane * 2][kl]     = pack4(v, qs);
        ts[lane * 2 + 1][kl] = pack4(v + 4, qs);
        if (lane == 0) g_se2[k] = -2.0f * amax * (1.0f / 127.0f);
    }
    __syncthreads();
    #pragma unroll
    for (int it = 0; it < 8; ++it) {
        int lin = tid + it * 256;
        int d4 = lin >> 5, kl = lin & 31;
        g_eqT[(size_t)d4 * KK + k0 + kl] = ts[d4][kl];
    }
}

// ---------------- main: int8 dp4a screen + exact fp32 rescore ----------------
// Conflict-free layout: warp w owns n-quarter [w*32, w*32+32), all 64 m.
// lane: my=lane>>2 (m-group of 8), tx2=lane&3 (n-subgroup of 8).
// A col-swizzled at stride 68 (1 wf/load), B per-warp 128B contiguous (1 wf).
__global__ void __launch_bounds__(128, 4)
vq_dp4a_kernel(const float* __restrict__ zf, const float* __restrict__ ef) {
    extern __shared__ char smem[];
    uint32_t* As = (uint32_t*)(smem + SM_A);    // [d4][ALD] swizzled cols
    uint32_t* Bs = (uint32_t*)(smem + SM_B);    // [buf][dl][n]
    uint16_t* candA = (uint16_t*)(smem + SM_CAND);

    int tid = threadIdx.x;
    int w = tid >> 5, lane = tid & 31;
    int my = lane >> 2, tx2 = lane & 3;
    int sub = w * 4 + tx2;                      // 16 sublists per row
    int mBase = blockIdx.x * BM;

    if (tid == 0) *(int*)(smem + SM_OVFN) = 0;

    // ---- fill As[d4][swzA(m)] ----
    {
        const uint32_t* zq = g_zq + (size_t)mBase * 64;
        #pragma unroll
        for (int it = 0; it < 8; ++it) {
            int lin = tid + it * 128;          // 0..1023
            int m = lin & 63, ug = lin >> 6;   // ug 0..15
            uint4 v = *(const uint4*)(zq + (size_t)m * 64 + ug * 4);
            int col = swzA(m);
            As[(ug * 4 + 0) * ALD + col] = v.x;
            As[(ug * 4 + 1) * ALD + col] = v.y;
            As[(ug * 4 + 2) * ALD + col] = v.z;
            As[(ug * 4 + 3) * ALD + col] = v.w;
        }
    }

    float szr[8];
    #pragma unroll
    for (int i = 0; i < 8; ++i) szr[i] = g_sz[mBase + my * 8 + i];

    float runmin[8];
    int   cnt[8];
    #pragma unroll
    for (int i = 0; i < 8; ++i) { runmin[i] = __int_as_float(0x7f800000); cnt[i] = 0; }

    __syncthreads();

    int dl0 = tid >> 4, nq = (tid & 15) * 8;   // B-fill slot: 8 u32 per thread
    const uint32_t* erow = g_eqT + (size_t)dl0 * KK + nq;
    int aoff = my * 8 + ((my >> 2) << 2);      // swizzled A chunk base (u32)
    int boff = w * 32 + tx2 * 8;               // this thread's B cols (u32)

    // prefetch tile 0, chunk 0
    uint4 p0 = *(const uint4*)erow;
    uint4 p1 = *(const uint4*)(erow + 4);

    #pragma unroll 1
    for (int t = 0; t < NTT; ++t) {
        int acc[8][8];
        #pragma unroll
        for (int i = 0; i < 8; ++i)
            #pragma unroll
            for (int j = 0; j < 8; ++j) acc[i][j] = 0;

        const uint32_t* ebase = erow + t * BN;
        *(uint4*)(Bs + dl0 * BN + nq)     = p0;
        *(uint4*)(Bs + dl0 * BN + nq + 4) = p1;
        __syncthreads();

        #pragma unroll 1
        for (int c = 0; c < NCH; ++c) {
            const uint32_t* Bc = Bs + (c & 1) * (8 * BN);
            if (c + 1 < NCH) {
                p0 = *(const uint4*)(ebase + (size_t)(c + 1) * 8 * KK);
                p1 = *(const uint4*)(ebase + (size_t)(c + 1) * 8 * KK + 4);
            } else if (t + 1 < NTT) {
                p0 = *(const uint4*)(ebase + BN);
                p1 = *(const uint4*)(ebase + BN + 4);
            }
            #pragma unroll
            for (int dl = 0; dl < 8; ++dl) {
                const uint32_t* Ar = As + (c * 8 + dl) * ALD + aoff;
                uint4 a0 = *(const uint4*)Ar;
                uint4 a1 = *(const uint4*)(Ar + 4);
                const uint32_t* Br = Bc + dl * BN + boff;
                uint4 b0 = *(const uint4*)Br;
                uint4 b1 = *(const uint4*)(Br + 4);
                int aa[8] = {(int)a0.x, (int)a0.y, (int)a0.z, (int)a0.w,
                             (int)a1.x, (int)a1.y, (int)a1.z, (int)a1.w};
                int bb[8] = {(int)b0.x, (int)b0.y, (int)b0.z, (int)b0.w,
                             (int)b1.x, (int)b1.y, (int)b1.z, (int)b1.w};
                #pragma unroll
                for (int i = 0; i < 8; ++i)
                    #pragma unroll
                    for (int j = 0; j < 8; ++j)
                        acc[i][j] = __dp4a(aa[i], bb[j], acc[i][j]);
            }
            if (c + 1 < NCH) {
                uint32_t* Bn = Bs + ((c + 1) & 1) * (8 * BN) + dl0 * BN + nq;
                *(uint4*)Bn       = p0;
                *(uint4*)(Bn + 4) = p1;
                __syncthreads();
            }
        }

        // epilogue: quad-shared runmin (xor 1,2), inline margin compare
        const float4* se2p = (const float4*)(g_se2 + t * BN + boff);
        float4 s20 = se2p[0], s21 = se2p[1];
        float se2a[8] = {s20.x, s20.y, s20.z, s20.w, s21.x, s21.y, s21.z, s21.w};
        const float4* e2p = (const float4*)(g_e2 + t * BN + boff);
        float4 e20 = e2p[0], e21 = e2p[1];
        float e2a[8] = {e20.x, e20.y, e20.z, e20.w, e21.x, e21.y, e21.z, e21.w};

        if (t == 0) {     // min-only pre-pass so runmin is finite & quad-global
            #pragma unroll
            for (int j = 0; j < 8; ++j)
                #pragma unroll
                for (int i = 0; i < 8; ++i) {
                    float sc = fmaf(szr[i] * se2a[j], (float)acc[i][j], e2a[j]);
                    runmin[i] = fminf(runmin[i], sc);
                }
            #pragma unroll
            for (int i = 0; i < 8; ++i) {
                float v = runmin[i];
                v = fminf(v, __shfl_xor_sync(0xffffffffu, v, 1));
                v = fminf(v, __shfl_xor_sync(0xffffffffu, v, 2));
                runmin[i] = v;
            }
        }

        #pragma unroll
        for (int j = 0; j < 8; ++j) {
            int k = t * BN + boff + j;
            #pragma unroll
            for (int i = 0; i < 8; ++i) {
                float sc = fmaf(szr[i] * se2a[j], (float)acc[i][j], e2a[j]);
                // subset-local threshold is safe: runmin >= true_min - E and
                // sc(k*) <= true_min + E, so k* passes with MARGIN >= 2E.
                if (sc <= runmin[i] + MARGIN) {
                    if (cnt[i] < CAP)
                        candA[((my * 8 + i) * 16 + sub) * CAP + cnt[i]] = (uint16_t)k;
                    cnt[i]++;
                }
                runmin[i] = fminf(runmin[i], sc);
            }
        }
        #pragma unroll
        for (int i = 0; i < 8; ++i) {
            float v = runmin[i];
            v = fminf(v, __shfl_xor_sync(0xffffffffu, v, 1));
            v = fminf(v, __shfl_xor_sync(0xffffffffu, v, 2));
            runmin[i] = v;
        }
    }

    // publish counts
    #pragma unroll
    for (int i = 0; i < 8; ++i)
        ((uint8_t*)(smem + SM_CNT))[(my * 8 + i) * 16 + sub] =
            (uint8_t)(cnt[i] > CAP ? CAP + 1 : cnt[i]);
    __syncthreads();

    // ---- exact fp32 rescore (verbatim proven arithmetic) ----
    if (tid < BM) {
        int rr = tid;
        int rowG = mBase + rr;
        const uint8_t* cp = (const uint8_t*)(smem + SM_CNT) + rr * 16;
        bool ovf = false;
        #pragma unroll
        for (int s = 0; s < 16; ++s) ovf |= (cp[s] > CAP);
        if (ovf) {
            int s = atomicAdd((int*)(smem + SM_OVFN), 1);
            ((int*)(smem + SM_OVFR))[s] = rr;
        } else {
            const float* zr = zf + (size_t)rowG * DD;
            float z2 = g_z2[rowG];
            uint32_t bestBits = 0xffffffffu; int bestK = 0;
            for (int s = 0; s < 16; ++s) {
                int c = cp[s];
                for (int i2 = 0; i2 < c; ++i2) {
                    int k = candA[(rr * 16 + s) * CAP + i2];
                    const float* er = ef + (size_t)k * DD;
                    float dot = 0.0f;
                    #pragma unroll 4
                    for (int d4 = 0; d4 < DD / 4; ++d4) {
                        float4 zv = ((const float4*)zr)[d4];
                        float4 ev = ((const float4*)er)[d4];
                        dot = fmaf(zv.x, ev.x, dot);
                        dot = fmaf(zv.y, ev.y, dot);
                        dot = fmaf(zv.z, ev.z, dot);
                        dot = fmaf(zv.w, ev.w, dot);
                    }
                    float t1 = z2 + g_e2[k];
                    float dist = t1 - 2.0f * dot;
                    uint32_t bits = __float_as_uint(dist);
                    if (bits < bestBits || (bits == bestBits && k < bestK)) {
                        bestBits = bits; bestK = k;
                    }
                }
            }
            g_idx[rowG] = bestK;
        }
    }
    __syncthreads();

    // ---- rare overflow fallback: cooperative exact full-row scan ----
    int novf = *(int*)(smem + SM_OVFN);
    unsigned long long* pack = (unsigned long long*)(smem + SM_PACK);
    for (int o = 0; o < novf; ++o) {
        int rr = ((int*)(smem + SM_OVFR))[o];
        int rG = mBase + rr;
        if (tid == 0) *pack = 0xffffffffffffffffULL;
        __syncthreads();
        const float* zr = zf + (size_t)rG * DD;
        float z2 = g_z2[rG];
        for (int k = tid; k < KK; k += 128) {
            const float* er = ef + (size_t)k * DD;
            float dot = 0.0f;
            #pragma unroll 4
            for (int d4 = 0; d4 < DD / 4; ++d4) {
                float4 zv = ((const float4*)zr)[d4];
                float4 ev = ((const float4*)er)[d4];
                dot = fmaf(zv.x, ev.x, dot);
                dot = fmaf(zv.y, ev.y, dot);
                dot = fmaf(zv.z, ev.z, dot);
                dot = fmaf(zv.w, ev.w, dot);
            }
            float t1 = z2 + g_e2[k];
            float dist = t1 - 2.0f * dot;
            unsigned long long pq =
                ((unsigned long long)__float_as_uint(dist) << 32) | (unsigned)k;
            atomicMin(pack, pq);
        }
        __syncthreads();
        if (tid == 0) g_idx[rG] = (int)(*pack & 0xffffffffu);
        __syncthreads();
    }
}

// ---------------- gather + writeout ----------------
__global__ void writeout_kernel(const float* __restrict__ e, float* __restrict__ out,
                                long long q_off, long long st_off, long long idx_off) {
    int row  = blockIdx.x * 8 + (threadIdx.x >> 5);
    int lane = threadIdx.x & 31;
    int idx  = g_idx[row];
    const float4* src = (const float4*)(e + (size_t)idx * DD);
    #pragma unroll
    for (int i = 0; i < 2; ++i) {
        float4 v = src[lane + i * 32];
        if (q_off >= 0)  ((float4*)(out + q_off))[(size_t)row * 64 + lane + i * 32] = v;
        if (st_off >= 0) ((float4*)(out + st_off))[(size_t)row * 64 + lane + i * 32] = v;
    }
    if (idx_off >= 0 && lane == 0) out[idx_off + row] = (float)idx;
}

extern "C" void kernel_launch(void* const* d_in, const int* in_sizes, int n_in,
                              void* d_out, int out_size) {
    const float* z = (const float*)d_in[0];
    const float* e = (const float*)d_in[1];
    float* out = (float*)d_out;

    cudaFuncSetAttribute(vq_dp4a_kernel,
                         cudaFuncAttributeMaxDynamicSharedMemorySize, SMEM_BYTES);

    prep_z_kernel<<<NN / 8, 256>>>(z);
    row_norm_kernel<<<KK / 8, 256>>>(e, 1);
    quant_eT_kernel<<<KK / 32, 256>>>(e);

    vq_dp4a_kernel<<<NN / BM, 128, SMEM_BYTES>>>(z, e);

    long long sz = out_size, pos = 0;
    long long q_off = -1, st_off = -1, idx_off = -1;
    if (sz - pos >= (long long)NN * DD) { q_off = pos;  pos += (long long)NN * DD; }
    if (sz - pos >= (long long)NN * DD) { st_off = pos; pos += (long long)NN * DD; }
    if (sz - pos >= NN)                 { idx_off = pos; }
    writeout_kernel<<<NN / 8, 256>>>(e, out, q_off, st_off, idx_off);
}

// round 15
// speedup vs baseline: 7.4109x; 7.4109x over previous
#include <cuda_runtime.h>
#include <cstdint>

#define NN 65536
#define KK 8192
#define DD 256
#define BM 64
#define BN 128
#define NTT (KK/BN)      // 64 n-tiles
#define NCH 8            // chunks of 8 d4 (32 dims)
#define MARGIN 6.0e-4f
#define CAP 8

// smem byte offsets
#define SM_A     0          // u32[64 d4][64 m]              16384
#define SM_B     16384      // u32[2][8 dl][128 n]            8192
#define SM_CAND  24576      // u16[64 m][16 tx][CAP]         16384
#define SM_CNT   40960      // u8[64][16]                     1024
#define SM_OVFN  41984
#define SM_OVFR  41988      // int[64]
#define SM_PACK  42248      // 8B aligned
#define SMEM_BYTES 42256

__device__ float    g_z2[NN];
__device__ float    g_e2[KK];
__device__ float    g_sz[NN];        // z row scale (amax/127)
__device__ float    g_se2[KK];       // -2 * e row scale
__device__ int      g_idx[NN];
__device__ uint32_t g_zq[(size_t)NN * (DD/4)];          // packed int8 [n][d4]
__device__ uint32_t g_eqT[(size_t)(DD/4) * KK];         // packed int8 [d4][k]

// B slot swizzle: each dl-row = 32 16B slots; slot s placed at s ^ ((s>>3)&3).
// Bijection; per 8-lane phase all 8 bank-quads hit exactly once (desk-checked).
__device__ __forceinline__ int bswz(int s) { return (s ^ ((s >> 3) & 3)) << 2; }

__device__ __forceinline__ uint32_t pack4(const float* v, float qs) {
    uint32_t r = 0;
    #pragma unroll
    for (int i = 0; i < 4; ++i) {
        int q = __float2int_rn(v[i] * qs);
        q = max(-127, min(127, q));
        r |= (uint32_t)(q & 0xff) << (i * 8);
    }
    return r;
}

// ---------------- prep kernels (proven) ----------------
__global__ void prep_z_kernel(const float* __restrict__ x) {
    int row  = blockIdx.x * 8 + (threadIdx.x >> 5);
    int lane = threadIdx.x & 31;
    const float* p = x + (size_t)row * DD;
    double s = 0.0;
    #pragma unroll
    for (int i = 0; i < DD / 32; ++i) {
        float v = p[lane + i * 32];
        float q = v * v;
        s += (double)q;
    }
    #pragma unroll
    for (int o = 16; o; o >>= 1) s += __shfl_xor_sync(0xffffffffu, s, o);
    if (lane == 0) g_z2[row] = (float)s;
    const float4* p4 = (const float4*)p;
    float4 v0 = p4[lane * 2], v1 = p4[lane * 2 + 1];
    float v[8] = {v0.x, v0.y, v0.z, v0.w, v1.x, v1.y, v1.z, v1.w};
    float amax = 0.0f;
    #pragma unroll
    for (int i = 0; i < 8; ++i) amax = fmaxf(amax, fabsf(v[i]));
    #pragma unroll
    for (int o = 16; o; o >>= 1) amax = fmaxf(amax, __shfl_xor_sync(0xffffffffu, amax, o));
    float qs = amax > 0.0f ? 127.0f / amax : 0.0f;
    g_zq[(size_t)row * 64 + lane * 2]     = pack4(v, qs);
    g_zq[(size_t)row * 64 + lane * 2 + 1] = pack4(v + 4, qs);
    if (lane == 0) g_sz[row] = amax * (1.0f / 127.0f);
}

__global__ void row_norm_kernel(const float* __restrict__ x, int which) {
    int row  = blockIdx.x * 8 + (threadIdx.x >> 5);
    int lane = threadIdx.x & 31;
    const float* p = x + (size_t)row * DD;
    double s = 0.0;
    #pragma unroll
    for (int i = 0; i < DD / 32; ++i) {
        float v = p[lane + i * 32];
        float q = v * v;
        s += (double)q;
    }
    #pragma unroll
    for (int o = 16; o; o >>= 1) s += __shfl_xor_sync(0xffffffffu, s, o);
    if (lane == 0) { if (which) g_e2[row] = (float)s; else g_z2[row] = (float)s; }
}

__global__ void quant_eT_kernel(const float* __restrict__ e) {
    __shared__ uint32_t ts[64][33];
    int tid = threadIdx.x, wid = tid >> 5, lane = tid & 31;
    int k0 = blockIdx.x * 32;
    #pragma unroll
    for (int r = 0; r < 4; ++r) {
        int kl = wid * 4 + r;
        int k = k0 + kl;
        const float4* p = (const float4*)(e + (size_t)k * DD);
        float4 v0 = p[lane * 2], v1 = p[lane * 2 + 1];
        float v[8] = {v0.x, v0.y, v0.z, v0.w, v1.x, v1.y, v1.z, v1.w};
        float amax = 0.0f;
        #pragma unroll
        for (int i = 0; i < 8; ++i) amax = fmaxf(amax, fabsf(v[i]));
        #pragma unroll
        for (int o = 16; o; o >>= 1) amax = fmaxf(amax, __shfl_xor_sync(0xffffffffu, amax, o));
        float qs = amax > 0.0f ? 127.0f / amax : 0.0f;
        ts[lane * 2][kl]     = pack4(v, qs);
        ts[lane * 2 + 1][kl] = pack4(v + 4, qs);
        if (lane == 0) g_se2[k] = -2.0f * amax * (1.0f / 127.0f);
    }
    __syncthreads();
    #pragma unroll
    for (int it = 0; it < 8; ++it) {
        int lin = tid + it * 256;
        int d4 = lin >> 5, kl = lin & 31;
        g_eqT[(size_t)d4 * KK + k0 + kl] = ts[d4][kl];
    }
}

// ---------------- main: int8 dp4a screen + exact fp32 rescore ----------------
// R12 structure verbatim; ONLY change: B smem placement slot-XOR swizzled to
// kill the 2-way bank conflicts on B loads/stores.
__global__ void __launch_bounds__(128, 4)
vq_dp4a_kernel(const float* __restrict__ zf, const float* __restrict__ ef) {
    extern __shared__ char smem[];
    uint32_t* As = (uint32_t*)(smem + SM_A);    // [d4][m]
    uint32_t* Bs = (uint32_t*)(smem + SM_B);    // [buf][dl][slots swizzled]
    uint16_t* candA = (uint16_t*)(smem + SM_CAND);

    int tid = threadIdx.x;
    int tx = tid & 15, ty = tid >> 4;           // tx: 8 n-cols, ty: 8 m-rows
    int mBase = blockIdx.x * BM;

    if (tid == 0) *(int*)(smem + SM_OVFN) = 0;

    // ---- fill As[d4][m] ----
    {
        const uint32_t* zq = g_zq + (size_t)mBase * 64;
        #pragma unroll
        for (int it = 0; it < 8; ++it) {
            int lin = tid + it * 128;          // 0..1023
            int m = lin & 63, ug = lin >> 6;   // ug 0..15
            uint4 v = *(const uint4*)(zq + (size_t)m * 64 + ug * 4);
            As[(ug * 4 + 0) * BM + m] = v.x;
            As[(ug * 4 + 1) * BM + m] = v.y;
            As[(ug * 4 + 2) * BM + m] = v.z;
            As[(ug * 4 + 3) * BM + m] = v.w;
        }
    }

    float szr[8];
    #pragma unroll
    for (int i = 0; i < 8; ++i) szr[i] = g_sz[mBase + ty * 8 + i];

    float runmin[8];
    int   cnt[8];
    #pragma unroll
    for (int i = 0; i < 8; ++i) { runmin[i] = __int_as_float(0x7f800000); cnt[i] = 0; }

    __syncthreads();

    int dl0 = tid >> 4, nq = (tid & 15) * 8;   // B-fill: 8 u32 (2 slots)/thread
    const uint32_t* erow = g_eqT + (size_t)dl0 * KK + nq;
    // swizzled fill columns (slots 2*(tid&15), 2*(tid&15)+1)
    int fcA = bswz((tid & 15) * 2);
    int fcB = bswz((tid & 15) * 2 + 1);
    // swizzled read columns (slots 2*tx, 2*tx+1)
    int rc0 = bswz(tx * 2);
    int rc1 = bswz(tx * 2 + 1);

    // prefetch tile 0, chunk 0
    uint4 p0 = *(const uint4*)erow;
    uint4 p1 = *(const uint4*)(erow + 4);

    #pragma unroll 1
    for (int t = 0; t < NTT; ++t) {
        int acc[8][8];
        #pragma unroll
        for (int i = 0; i < 8; ++i)
            #pragma unroll
            for (int j = 0; j < 8; ++j) acc[i][j] = 0;

        const uint32_t* ebase = erow + t * BN;
        *(uint4*)(Bs + dl0 * BN + fcA) = p0;
        *(uint4*)(Bs + dl0 * BN + fcB) = p1;
        __syncthreads();

        #pragma unroll 1
        for (int c = 0; c < NCH; ++c) {
            const uint32_t* Bc = Bs + (c & 1) * (8 * BN);
            if (c + 1 < NCH) {
                p0 = *(const uint4*)(ebase + (size_t)(c + 1) * 8 * KK);
                p1 = *(const uint4*)(ebase + (size_t)(c + 1) * 8 * KK + 4);
            } else if (t + 1 < NTT) {
                p0 = *(const uint4*)(ebase + BN);
                p1 = *(const uint4*)(ebase + BN + 4);
            }
            #pragma unroll
            for (int dl = 0; dl < 8; ++dl) {
                const uint32_t* Ar = As + (c * 8 + dl) * BM + ty * 8;
                uint4 a0 = *(const uint4*)Ar;
                uint4 a1 = *(const uint4*)(Ar + 4);
                const uint32_t* Br = Bc + dl * BN;
                uint4 b0 = *(const uint4*)(Br + rc0);
                uint4 b1 = *(const uint4*)(Br + rc1);
                int aa[8] = {(int)a0.x, (int)a0.y, (int)a0.z, (int)a0.w,
                             (int)a1.x, (int)a1.y, (int)a1.z, (int)a1.w};
                int bb[8] = {(int)b0.x, (int)b0.y, (int)b0.z, (int)b0.w,
                             (int)b1.x, (int)b1.y, (int)b1.z, (int)b1.w};
                #pragma unroll
                for (int i = 0; i < 8; ++i)
                    #pragma unroll
                    for (int j = 0; j < 8; ++j)
                        acc[i][j] = __dp4a(aa[i], bb[j], acc[i][j]);
            }
            if (c + 1 < NCH) {
                uint32_t* Bn = Bs + ((c + 1) & 1) * (8 * BN) + dl0 * BN;
                *(uint4*)(Bn + fcA) = p0;
                *(uint4*)(Bn + fcB) = p1;
                __syncthreads();
            }
        }

        // epilogue: row-global runmin (shfl-shared), inline margin compare
        const float4* se2p = (const float4*)(g_se2 + t * BN + tx * 8);
        float4 s20 = se2p[0], s21 = se2p[1];
        float se2a[8] = {s20.x, s20.y, s20.z, s20.w, s21.x, s21.y, s21.z, s21.w};
        const float4* e2p = (const float4*)(g_e2 + t * BN + tx * 8);
        float4 e20 = e2p[0], e21 = e2p[1];
        float e2a[8] = {e20.x, e20.y, e20.z, e20.w, e21.x, e21.y, e21.z, e21.w};

        if (t == 0) {     // min-only pre-pass so runmin is finite & row-global
            #pragma unroll
            for (int j = 0; j < 8; ++j)
                #pragma unroll
                for (int i = 0; i < 8; ++i) {
                    float sc = fmaf(szr[i] * se2a[j], (float)acc[i][j], e2a[j]);
                    runmin[i] = fminf(runmin[i], sc);
                }
            #pragma unroll
            for (int i = 0; i < 8; ++i) {
                float v = runmin[i];
                #pragma unroll
                for (int o = 1; o < 16; o <<= 1)
                    v = fminf(v, __shfl_xor_sync(0xffffffffu, v, o));
                runmin[i] = v;
            }
        }

        #pragma unroll
        for (int j = 0; j < 8; ++j) {
            int k = t * BN + tx * 8 + j;
            #pragma unroll
            for (int i = 0; i < 8; ++i) {
                float sc = fmaf(szr[i] * se2a[j], (float)acc[i][j], e2a[j]);
                if (sc <= runmin[i] + MARGIN) {
                    if (cnt[i] < CAP)
                        candA[((ty * 8 + i) * 16 + tx) * CAP + cnt[i]] = (uint16_t)k;
                    cnt[i]++;
                }
                runmin[i] = fminf(runmin[i], sc);
            }
        }
        #pragma unroll
        for (int i = 0; i < 8; ++i) {
            float v = runmin[i];
            #pragma unroll
            for (int o = 1; o < 16; o <<= 1)
                v = fminf(v, __shfl_xor_sync(0xffffffffu, v, o));
            runmin[i] = v;
        }
    }

    // publish counts
    #pragma unroll
    for (int i = 0; i < 8; ++i)
        ((uint8_t*)(smem + SM_CNT))[(ty * 8 + i) * 16 + tx] =
            (uint8_t)(cnt[i] > CAP ? CAP + 1 : cnt[i]);
    __syncthreads();

    // ---- exact fp32 rescore (verbatim proven arithmetic) ----
    if (tid < BM) {
        int rr = tid;
        int rowG = mBase + rr;
        const uint8_t* cp = (const uint8_t*)(smem + SM_CNT) + rr * 16;
        bool ovf = false;
        #pragma unroll
        for (int s = 0; s < 16; ++s) ovf |= (cp[s] > CAP);
        if (ovf) {
            int s = atomicAdd((int*)(smem + SM_OVFN), 1);
            ((int*)(smem + SM_OVFR))[s] = rr;
        } else {
            const float* zr = zf + (size_t)rowG * DD;
            float z2 = g_z2[rowG];
            uint32_t bestBits = 0xffffffffu; int bestK = 0;
            for (int s = 0; s < 16; ++s) {
                int c = cp[s];
                for (int i2 = 0; i2 < c; ++i2) {
                    int k = candA[(rr * 16 + s) * CAP + i2];
                    const float* er = ef + (size_t)k * DD;
                    float dot = 0.0f;
                    #pragma unroll 4
                    for (int d4 = 0; d4 < DD / 4; ++d4) {
                        float4 zv = ((const float4*)zr)[d4];
                        float4 ev = ((const float4*)er)[d4];
                        dot = fmaf(zv.x, ev.x, dot);
                        dot = fmaf(zv.y, ev.y, dot);
                        dot = fmaf(zv.z, ev.z, dot);
                        dot = fmaf(zv.w, ev.w, dot);
                    }
                    float t1 = z2 + g_e2[k];
                    float dist = t1 - 2.0f * dot;
                    uint32_t bits = __float_as_uint(dist);
                    if (bits < bestBits || (bits == bestBits && k < bestK)) {
                        bestBits = bits; bestK = k;
                    }
                }
            }
            g_idx[rowG] = bestK;
        }
    }
    __syncthreads();

    // ---- rare overflow fallback: cooperative exact full-row scan ----
    int novf = *(int*)(smem + SM_OVFN);
    unsigned long long* pack = (unsigned long long*)(smem + SM_PACK);
    for (int o = 0; o < novf; ++o) {
        int rr = ((int*)(smem + SM_OVFR))[o];
        int rG = mBase + rr;
        if (tid == 0) *pack = 0xffffffffffffffffULL;
        __syncthreads();
        const float* zr = zf + (size_t)rG * DD;
        float z2 = g_z2[rG];
        for (int k = tid; k < KK; k += 128) {
            const float* er = ef + (size_t)k * DD;
            float dot = 0.0f;
            #pragma unroll 4
            for (int d4 = 0; d4 < DD / 4; ++d4) {
                float4 zv = ((const float4*)zr)[d4];
                float4 ev = ((const float4*)er)[d4];
                dot = fmaf(zv.x, ev.x, dot);
                dot = fmaf(zv.y, ev.y, dot);
                dot = fmaf(zv.z, ev.z, dot);
                dot = fmaf(zv.w, ev.w, dot);
            }
            float t1 = z2 + g_e2[k];
            float dist = t1 - 2.0f * dot;
            unsigned long long pq =
                ((unsigned long long)__float_as_uint(dist) << 32) | (unsigned)k;
            atomicMin(pack, pq);
        }
        __syncthreads();
        if (tid == 0) g_idx[rG] = (int)(*pack & 0xffffffffu);
        __syncthreads();
    }
}

// ---------------- gather + writeout ----------------
__global__ void writeout_kernel(const float* __restrict__ e, float* __restrict__ out,
                                long long q_off, long long st_off, long long idx_off) {
    int row  = blockIdx.x * 8 + (threadIdx.x >> 5);
    int lane = threadIdx.x & 31;
    int idx  = g_idx[row];
    const float4* src = (const float4*)(e + (size_t)idx * DD);
    #pragma unroll
    for (int i = 0; i < 2; ++i) {
        float4 v = src[lane + i * 32];
        if (q_off >= 0)  ((float4*)(out + q_off))[(size_t)row * 64 + lane + i * 32] = v;
        if (st_off >= 0) ((float4*)(out + st_off))[(size_t)row * 64 + lane + i * 32] = v;
    }
    if (idx_off >= 0 && lane == 0) out[idx_off + row] = (float)idx;
}

extern "C" void kernel_launch(void* const* d_in, const int* in_sizes, int n_in,
                              void* d_out, int out_size) {
    const float* z = (const float*)d_in[0];
    const float* e = (const float*)d_in[1];
    float* out = (float*)d_out;

    cudaFuncSetAttribute(vq_dp4a_kernel,
                         cudaFuncAttributeMaxDynamicSharedMemorySize, SMEM_BYTES);

    prep_z_kernel<<<NN / 8, 256>>>(z);
    row_norm_kernel<<<KK / 8, 256>>>(e, 1);
    quant_eT_kernel<<<KK / 32, 256>>>(e);

    vq_dp4a_kernel<<<NN / BM, 128, SMEM_BYTES>>>(z, e);

    long long sz = out_size, pos = 0;
    long long q_off = -1, st_off = -1, idx_off = -1;
    if (sz - pos >= (long long)NN * DD) { q_off = pos;  pos += (long long)NN * DD; }
    if (sz - pos >= (long long)NN * DD) { st_off = pos; pos += (long long)NN * DD; }
    if (sz - pos >= NN)                 { idx_off = pos; }
    writeout_kernel<<<NN / 8, 256>>>(e, out, q_off, st_off, idx_off);
}